// round 6
// baseline (speedup 1.0000x reference)
#include <cuda_runtime.h>

#define NROI 1024
#define NB   8
#define FH   160
#define FW   160
#define CC   256
#define CROPN 14
#define PO   7

// Per-ROI params: {b, ybase, ystep, xbase} / {xstep, -, -, -}
__device__ float4 g_rp[NROI * 2];
__device__ int    g_perm[NROI];

// Fused setup: per-ROI param precompute + bucket sort by image id, one block.
__global__ __launch_bounds__(NROI) void roi_setup_kernel(
    const float* __restrict__ rois,
    const float* __restrict__ iminfo)
{
    __shared__ int cnt[NB];
    __shared__ int off[NB];
    const int i = threadIdx.x;               // 0..1023, one ROI each

    const float rid = rois[i * 5 + 0];
    const float rx1 = rois[i * 5 + 1];
    const float ry1 = rois[i * 5 + 2];
    const float rx2 = rois[i * 5 + 3];
    const float ry2 = rois[i * 5 + 4];
    const float imh = iminfo[i * 2 + 0];
    const float imw = iminfo[i * 2 + 1];

    const float ybase = (ry1 / imh) * (float)(FH - 1);
    const float xbase = (rx1 / imw) * (float)(FW - 1);
    const float ystep = ((ry2 - ry1) / imh) * (float)(FH - 1) / (float)(CROPN - 1);
    const float xstep = ((rx2 - rx1) / imw) * (float)(FW - 1) / (float)(CROPN - 1);

    g_rp[i * 2 + 0] = make_float4(rid, ybase, ystep, xbase);
    g_rp[i * 2 + 1] = make_float4(xstep, 0.0f, 0.0f, 0.0f);

    // bucket sort by image id -> g_perm (concurrent waves share one image in L2)
    if (i < NB) cnt[i] = 0;
    __syncthreads();
    const int b = (int)rid;
    atomicAdd(&cnt[b], 1);
    __syncthreads();
    if (i == 0) {
        int s = 0;
        for (int k = 0; k < NB; ++k) { off[k] = s; s += cnt[k]; }
    }
    __syncthreads();
    const int pos = atomicAdd(&off[b], 1);
    g_perm[pos] = i;
}

// One block per (sorted-roi, pooled-row). 448 threads = 7 px * 64 lanes.
// Thread lane t owns channels {t, t+64, t+128, t+192}: every warp-level
// scalar LDG covers exactly one 128B line (no within-LDG wavefront replays).
__global__ __launch_bounds__(448, 4) void roi_pool_kernel(
    const float* __restrict__ img,
    float* __restrict__ out)
{
    const int blk = blockIdx.x;
    const int sr  = blk / PO;
    const int py  = blk - sr * PO;
    const int roi = g_perm[sr];
    const int px  = threadIdx.x >> 6;        // 0..6
    const int t   = threadIdx.x & 63;        // lane within channel dim

    const float4 p0 = __ldg(&g_rp[roi * 2 + 0]);
    const float4 p1 = __ldg(&g_rp[roi * 2 + 1]);
    const int   b     = (int)p0.x;
    const float ybase = p0.y;
    const float ystep = p0.z;
    const float xbase = p0.w;
    const float xstep = p1.x;

    const float* imgb = img + (size_t)b * (FH * FW * CC) + t;

    float best0 = -3.402823466e38f;
    float best1 = -3.402823466e38f;
    float best2 = -3.402823466e38f;
    float best3 = -3.402823466e38f;

    #pragma unroll
    for (int dyi = 0; dyi < 2; ++dyi) {
        const int   iy = 2 * py + dyi;
        const float y  = fmaf((float)iy, ystep, ybase);
        const bool  vy = (y >= 0.0f) && (y <= (float)(FH - 1));
        const float yf = floorf(y);
        const float wy = y - yf;
        const int   yli = (int)fminf(fmaxf(yf,        0.0f), (float)(FH - 1));
        const int   yhi = (int)fminf(fmaxf(yf + 1.0f, 0.0f), (float)(FH - 1));

        const float* rowl = imgb + yli * (FW * CC);
        const float* rowh = imgb + yhi * (FW * CC);

        #pragma unroll
        for (int dxi = 0; dxi < 2; ++dxi) {
            const int   ix = 2 * px + dxi;
            const float x  = fmaf((float)ix, xstep, xbase);
            const bool  vx = (x >= 0.0f) && (x <= (float)(FW - 1));
            const float xf = floorf(x);
            const float wx = x - xf;
            const int   xli = (int)fminf(fmaxf(xf,        0.0f), (float)(FW - 1));
            const int   xhi = (int)fminf(fmaxf(xf + 1.0f, 0.0f), (float)(FW - 1));

            const float* atl = rowl + xli * CC;
            const float* atr = rowl + xhi * CC;
            const float* abl = rowh + xli * CC;
            const float* abr = rowh + xhi * CC;

            // 16 independent single-line loads, batched for MLP
            const float tl0 = __ldg(atl +   0), tl1 = __ldg(atl +  64),
                        tl2 = __ldg(atl + 128), tl3 = __ldg(atl + 192);
            const float tr0 = __ldg(atr +   0), tr1 = __ldg(atr +  64),
                        tr2 = __ldg(atr + 128), tr3 = __ldg(atr + 192);
            const float bl0 = __ldg(abl +   0), bl1 = __ldg(abl +  64),
                        bl2 = __ldg(abl + 128), bl3 = __ldg(abl + 192);
            const float br0 = __ldg(abr +   0), br1 = __ldg(abr +  64),
                        br2 = __ldg(abr + 128), br3 = __ldg(abr + 192);

            const bool ok = vy && vx;

            float top, bot, v;
            top = fmaf(tr0 - tl0, wx, tl0);
            bot = fmaf(br0 - bl0, wx, bl0);
            v   = fmaf(bot - top, wy, top);
            if (!ok) v = 0.0f;
            best0 = fmaxf(best0, v);

            top = fmaf(tr1 - tl1, wx, tl1);
            bot = fmaf(br1 - bl1, wx, bl1);
            v   = fmaf(bot - top, wy, top);
            if (!ok) v = 0.0f;
            best1 = fmaxf(best1, v);

            top = fmaf(tr2 - tl2, wx, tl2);
            bot = fmaf(br2 - bl2, wx, bl2);
            v   = fmaf(bot - top, wy, top);
            if (!ok) v = 0.0f;
            best2 = fmaxf(best2, v);

            top = fmaf(tr3 - tl3, wx, tl3);
            bot = fmaf(br3 - bl3, wx, bl3);
            v   = fmaf(bot - top, wy, top);
            if (!ok) v = 0.0f;
            best3 = fmaxf(best3, v);
        }
    }

    float* o = out + ((size_t)(roi * PO + py) * PO + px) * CC + t;
    __stcs(o +   0, best0);
    __stcs(o +  64, best1);
    __stcs(o + 128, best2);
    __stcs(o + 192, best3);
}

extern "C" void kernel_launch(void* const* d_in, const int* in_sizes, int n_in,
                              void* d_out, int out_size)
{
    (void)in_sizes; (void)n_in; (void)out_size;
    const float* img    = (const float*)d_in[0];
    const float* rois   = (const float*)d_in[1];
    const float* iminfo = (const float*)d_in[2];
    float*       out    = (float*)d_out;

    roi_setup_kernel<<<1, NROI>>>(rois, iminfo);
    roi_pool_kernel<<<NROI * PO, 448>>>(img, out);
}

// round 7
// speedup vs baseline: 1.2249x; 1.2249x over previous
#include <cuda_runtime.h>

#define NROI 1024
#define NB   8
#define FH   160
#define FW   160
#define CC   256
#define CROPN 14
#define PO   7

// Per-ROI params: {b, ybase, ystep, xbase} / {xstep, -, -, -}
__device__ float4 g_rp[NROI * 2];
__device__ int    g_perm[NROI];

// Fused setup: per-ROI param precompute + bucket sort by image id, one block.
__global__ __launch_bounds__(NROI) void roi_setup_kernel(
    const float* __restrict__ rois,
    const float* __restrict__ iminfo)
{
    __shared__ int cnt[NB];
    __shared__ int off[NB];
    const int i = threadIdx.x;               // 0..1023, one ROI each

    const float rid = rois[i * 5 + 0];
    const float rx1 = rois[i * 5 + 1];
    const float ry1 = rois[i * 5 + 2];
    const float rx2 = rois[i * 5 + 3];
    const float ry2 = rois[i * 5 + 4];
    const float imh = iminfo[i * 2 + 0];
    const float imw = iminfo[i * 2 + 1];

    const float ybase = (ry1 / imh) * (float)(FH - 1);
    const float xbase = (rx1 / imw) * (float)(FW - 1);
    const float ystep = ((ry2 - ry1) / imh) * (float)(FH - 1) / (float)(CROPN - 1);
    const float xstep = ((rx2 - rx1) / imw) * (float)(FW - 1) / (float)(CROPN - 1);

    g_rp[i * 2 + 0] = make_float4(rid, ybase, ystep, xbase);
    g_rp[i * 2 + 1] = make_float4(xstep, 0.0f, 0.0f, 0.0f);

    // bucket sort by image id -> g_perm (concurrent waves share one image in L2)
    if (i < NB) cnt[i] = 0;
    __syncthreads();
    const int b = (int)rid;
    atomicAdd(&cnt[b], 1);
    __syncthreads();
    if (i == 0) {
        int s = 0;
        for (int k = 0; k < NB; ++k) { off[k] = s; s += cnt[k]; }
    }
    __syncthreads();
    const int pos = atomicAdd(&off[b], 1);
    g_perm[pos] = i;
}

// One block per (sorted-roi, pooled-row). 448 threads = 7 px * 64 lanes.
// Lane t owns channels {2t, 2t+1, 128+2t, 128+2t+1}: every tap is two
// LDG.64 (warp covers 256B = 2 L1 wavefronts each), the L1tex sweet spot
// between LDG.128 replay cost (2.07 cyc/extra wf) and LDG.32 dispatch floor.
__global__ __launch_bounds__(448, 4) void roi_pool_kernel(
    const float* __restrict__ img,
    float* __restrict__ out)
{
    const int blk = blockIdx.x;
    const int sr  = blk / PO;
    const int py  = blk - sr * PO;
    const int roi = g_perm[sr];
    const int px  = threadIdx.x >> 6;        // 0..6
    const int t   = threadIdx.x & 63;        // lane within channel dim

    const float4 p0 = __ldg(&g_rp[roi * 2 + 0]);
    const float4 p1 = __ldg(&g_rp[roi * 2 + 1]);
    const int   b     = (int)p0.x;
    const float ybase = p0.y;
    const float ystep = p0.z;
    const float xbase = p0.w;
    const float xstep = p1.x;

    // float2 view; lane t -> channels {2t, 2t+1} and {128+2t, 128+2t+1}
    const float2* imgb = (const float2*)(img + (size_t)b * (FH * FW * CC)) + t;

    float best0 = -3.402823466e38f;   // ch 2t
    float best1 = -3.402823466e38f;   // ch 2t+1
    float best2 = -3.402823466e38f;   // ch 128+2t
    float best3 = -3.402823466e38f;   // ch 128+2t+1

    #pragma unroll
    for (int dyi = 0; dyi < 2; ++dyi) {
        const int   iy = 2 * py + dyi;
        const float y  = fmaf((float)iy, ystep, ybase);
        const bool  vy = (y >= 0.0f) && (y <= (float)(FH - 1));
        const float yf = floorf(y);
        const float wy = y - yf;
        const int   yli = (int)fminf(fmaxf(yf,        0.0f), (float)(FH - 1));
        const int   yhi = (int)fminf(fmaxf(yf + 1.0f, 0.0f), (float)(FH - 1));

        const float2* rowl = imgb + yli * (FW * CC / 2);
        const float2* rowh = imgb + yhi * (FW * CC / 2);

        #pragma unroll
        for (int dxi = 0; dxi < 2; ++dxi) {
            const int   ix = 2 * px + dxi;
            const float x  = fmaf((float)ix, xstep, xbase);
            const bool  vx = (x >= 0.0f) && (x <= (float)(FW - 1));
            const float xf = floorf(x);
            const float wx = x - xf;
            const int   xli = (int)fminf(fmaxf(xf,        0.0f), (float)(FW - 1));
            const int   xhi = (int)fminf(fmaxf(xf + 1.0f, 0.0f), (float)(FW - 1));

            const float2* atl = rowl + xli * (CC / 2);
            const float2* atr = rowl + xhi * (CC / 2);
            const float2* abl = rowh + xli * (CC / 2);
            const float2* abr = rowh + xhi * (CC / 2);

            // 8 LDG.64; second-half address is a free +512B immediate
            const float2 tlA = __ldg(atl), tlB = __ldg(atl + 64);
            const float2 trA = __ldg(atr), trB = __ldg(atr + 64);
            const float2 blA = __ldg(abl), blB = __ldg(abl + 64);
            const float2 brA = __ldg(abr), brB = __ldg(abr + 64);

            const bool ok = vy && vx;
            float top, bot, v;

            top = fmaf(trA.x - tlA.x, wx, tlA.x);
            bot = fmaf(brA.x - blA.x, wx, blA.x);
            v   = fmaf(bot - top, wy, top);
            if (!ok) v = 0.0f;
            best0 = fmaxf(best0, v);

            top = fmaf(trA.y - tlA.y, wx, tlA.y);
            bot = fmaf(brA.y - blA.y, wx, blA.y);
            v   = fmaf(bot - top, wy, top);
            if (!ok) v = 0.0f;
            best1 = fmaxf(best1, v);

            top = fmaf(trB.x - tlB.x, wx, tlB.x);
            bot = fmaf(brB.x - blB.x, wx, blB.x);
            v   = fmaf(bot - top, wy, top);
            if (!ok) v = 0.0f;
            best2 = fmaxf(best2, v);

            top = fmaf(trB.y - tlB.y, wx, tlB.y);
            bot = fmaf(brB.y - blB.y, wx, blB.y);
            v   = fmaf(bot - top, wy, top);
            if (!ok) v = 0.0f;
            best3 = fmaxf(best3, v);
        }
    }

    float2* o = (float2*)(out + ((size_t)(roi * PO + py) * PO + px) * CC) + t;
    float2 s0; s0.x = best0; s0.y = best1;
    float2 s1; s1.x = best2; s1.y = best3;
    __stcs(o,      s0);
    __stcs(o + 64, s1);
}

extern "C" void kernel_launch(void* const* d_in, const int* in_sizes, int n_in,
                              void* d_out, int out_size)
{
    (void)in_sizes; (void)n_in; (void)out_size;
    const float* img    = (const float*)d_in[0];
    const float* rois   = (const float*)d_in[1];
    const float* iminfo = (const float*)d_in[2];
    float*       out    = (float*)d_out;

    roi_setup_kernel<<<1, NROI>>>(rois, iminfo);
    roi_pool_kernel<<<NROI * PO, 448>>>(img, out);
}